// round 6
// baseline (speedup 1.0000x reference)
#include <cuda_runtime.h>
#include <cstdint>
#include <cstddef>

typedef unsigned long long u64;

#define BATCH 8
#define SEQ   512
#define DIM   1024
#define NVOC  32064
#define NCTA  128
#define JT    8
#define KPAD  1028
#define RNN_THREADS 256
#define RNN_SMEM ((4*JT*KPAD + 2*BATCH*DIM) * 4)

// ---------------- scratch (device globals; no allocation allowed) ----------------
__device__ __align__(16) float g_h[2][2][BATCH][DIM];          // [layer][parity][b][d]
__device__ __align__(16) float g_rnn_out[BATCH * SEQ * DIM];   // 16 MB activations
__device__ unsigned g_bar_arrive;
__device__ unsigned g_bar_release;

// ---------------- packed f32x2 helpers (ptxas never emits FFMA2 from C++) --------
__device__ __forceinline__ void fmaX2(u64 &d, u64 a, u64 b) {
    asm("fma.rn.f32x2 %0, %1, %2, %0;" : "+l"(d) : "l"(a), "l"(b));
}
__device__ __forceinline__ u64 dup2(float s) {
    u64 d; asm("mov.b64 %0, {%1, %1};" : "=l"(d) : "f"(s)); return d;
}
__device__ __forceinline__ float lo32(u64 v) { return __uint_as_float((unsigned)v); }
__device__ __forceinline__ float hi32(u64 v) { return __uint_as_float((unsigned)(v >> 32)); }
__device__ __forceinline__ float sum2(u64 v) { return lo32(v) + hi32(v); }

// ------------- grid barrier: monotonic generations -> CUDA-graph-replay safe -----
__device__ __forceinline__ void grid_barrier() {
    __syncthreads();
    if (threadIdx.x == 0) {
        __threadfence();  // gpu scope: makes this CTA's stores visible chip-wide
        unsigned ticket = atomicAdd(&g_bar_arrive, 1u);
        unsigned gen = ticket / NCTA;
        if ((ticket % NCTA) == (NCTA - 1u)) {
            atomicAdd(&g_bar_release, 1u);
        } else {
            while (*((volatile unsigned*)&g_bar_release) <= gen) { }
        }
        __threadfence();
    }
    __syncthreads();
}

// x.w0 + h.w1 over this thread's 256-float chunk (ts in 0..3), fp32x2 packed
__device__ __forceinline__ float dot2x(const float* x, const float* w0,
                                       const float* h, const float* w1, int ts) {
    const ulonglong2* xp = (const ulonglong2*)x  + ts * 64;
    const ulonglong2* ap = (const ulonglong2*)w0 + ts * 64;
    const ulonglong2* hp = (const ulonglong2*)h  + ts * 64;
    const ulonglong2* bp = (const ulonglong2*)w1 + ts * 64;
    u64 a0 = 0ull, a1 = 0ull, a2 = 0ull, a3 = 0ull;
    #pragma unroll 8
    for (int i = 0; i < 64; i++) {
        ulonglong2 xv = xp[i], wv = ap[i];
        fmaX2(a0, xv.x, wv.x);
        fmaX2(a1, xv.y, wv.y);
        ulonglong2 hv = hp[i], uv = bp[i];
        fmaX2(a2, hv.x, uv.x);
        fmaX2(a3, hv.y, uv.y);
    }
    return sum2(a0) + sum2(a1) + sum2(a2) + sum2(a3);
}

// =====================================================================
// Persistent RNN kernel: 128 CTAs x 256 threads; CTA owns output cols
// [j0, j0+8). Weight slices cached in smem; activations staged per step.
// Thread -> (jj = col, tb = batch, ts = K-quarter).
// =====================================================================
__global__ void __launch_bounds__(RNN_THREADS, 1)
rnn_kernel(const int* __restrict__ tokens, const float* __restrict__ emb,
           const float* __restrict__ Wh, const float* __restrict__ Uh,
           const float* __restrict__ bias)
{
    extern __shared__ __align__(16) float smem[];
    float* sW0  = smem;
    float* sU0  = smem + 1 * JT * KPAD;
    float* sW1  = smem + 2 * JT * KPAD;
    float* sU1  = smem + 3 * JT * KPAD;
    float* sInp = smem + 4 * JT * KPAD;      // [BATCH][DIM]
    float* sH   = sInp + BATCH * DIM;        // [BATCH][DIM]
    __shared__ float sred[RNN_THREADS];

    const int tid = threadIdx.x;
    const int j0  = blockIdx.x * JT;
    const int jj  = tid & 7;
    const int tb  = (tid >> 3) & 7;
    const int ts  = tid >> 6;

    // cache transposed weight slices: s[j][k] = W[k][j0+j], row stride KPAD
    for (int idx = tid; idx < JT * DIM; idx += RNN_THREADS) {
        int k = idx >> 3, j = idx & 7;
        sW0[j * KPAD + k] = Wh[k * DIM + j0 + j];
        sU0[j * KPAD + k] = Uh[k * DIM + j0 + j];
        sW1[j * KPAD + k] = Wh[DIM * DIM + k * DIM + j0 + j];
        sU1[j * KPAD + k] = Uh[DIM * DIM + k * DIM + j0 + j];
    }
    // re-zero parity-0 hidden state every launch (it is dirty after a replay)
    if (tid < 64) {
        g_h[0][0][tid >> 3][j0 + (tid & 7)] = 0.f;
        g_h[1][0][tid >> 3][j0 + (tid & 7)] = 0.f;
    }
    const float b0 = bias[j0 + jj];
    const float b1 = bias[DIM + j0 + jj];
    grid_barrier();

    for (int t = 0; t < SEQ; t++) {
        const int p = t & 1;

        // ---------- layer 0: stage embedding (pad->0) + h0[p] ----------
        {
            float4* di = (float4*)sInp;
            float4* dh = (float4*)sH;
            const float4* hs = (const float4*)&g_h[0][p][0][0];
            for (int v = tid; v < (BATCH * DIM / 4); v += RNN_THREADS) {
                int bb = v >> 8;               // 256 float4 per batch row
                int kk = (v & 255) << 2;
                int tk = __ldg(tokens + bb * SEQ + t);
                float4 x = make_float4(0.f, 0.f, 0.f, 0.f);
                if (tk != 0) x = __ldg((const float4*)(emb + (size_t)tk * DIM + kk));
                di[v] = x;
                dh[v] = __ldcg(hs + v);        // bypass (possibly stale) L1
            }
        }
        __syncthreads();
        sred[tid] = dot2x(sInp + tb * DIM, sW0 + jj * KPAD,
                          sH   + tb * DIM, sU0 + jj * KPAD, ts);
        __syncthreads();
        if (ts == 0) {
            float s = sred[tid] + sred[tid + 64] + sred[tid + 128] + sred[tid + 192] + b0;
            g_h[0][p ^ 1][tb][j0 + jj] = tanhf(s);
        }
        grid_barrier();

        // ---------- layer 1 ----------
        {
            float4* di = (float4*)sInp;
            float4* dh = (float4*)sH;
            const float4* is = (const float4*)&g_h[0][p ^ 1][0][0];
            const float4* hs = (const float4*)&g_h[1][p][0][0];
            for (int v = tid; v < (BATCH * DIM / 4); v += RNN_THREADS) {
                di[v] = __ldcg(is + v);
                dh[v] = __ldcg(hs + v);
            }
        }
        __syncthreads();
        sred[tid] = dot2x(sInp + tb * DIM, sW1 + jj * KPAD,
                          sH   + tb * DIM, sU1 + jj * KPAD, ts);
        __syncthreads();
        if (ts == 0) {
            float s = sred[tid] + sred[tid + 64] + sred[tid + 128] + sred[tid + 192] + b1;
            float hv = tanhf(s);
            g_h[1][p ^ 1][tb][j0 + jj] = hv;
            g_rnn_out[(size_t)(tb * SEQ + t) * DIM + j0 + jj] = hv;
        }
        grid_barrier();
    }
}

// =====================================================================
// Projection: C[4096, 32064] = g_rnn_out[4096,1024] @ fc_w[1024,32064] + fc_b
// 128x128x8 tiles, 8x8 per thread, packed fma.rn.f32x2 (full fp32 rate).
// B stored pre-duplicated as u64 in smem (no per-FMA packing movs).
// Register prefetch hides the LDG under compute.
// =====================================================================
#define BM 128
#define BN 128
#define ASPAD 132   // 132 floats = 528 B row stride: 16B-aligned rows

__global__ void __launch_bounds__(256)
gemm_kernel(const float* __restrict__ Bw, const float* __restrict__ bias,
            float* __restrict__ C)
{
    const int N = NVOC, K = DIM;
    const float* __restrict__ A = g_rnn_out;

    __shared__ __align__(16) float As[8 * ASPAD];   // [k][m] transposed
    __shared__ __align__(16) u64   Bs[8 * BN];      // [k][n] duplicated pairs

    const int tid = threadIdx.x;
    const int tx = tid & 15, ty = tid >> 4;
    const int row0 = blockIdx.x * BM;               // M fast -> A L2-resident
    const int col0 = blockIdx.y * BN;

    const int arow = tid >> 1, acol = (tid & 1) << 2;
    const int brow = tid >> 5, bcol = (tid & 31) << 2;
    const bool bok = (col0 + bcol) < N;             // N%4==0: whole f4 valid/invalid

    u64 acc[32];
    #pragma unroll
    for (int i = 0; i < 32; i++) acc[i] = 0ull;

    const float* Aip = A + (size_t)(row0 + arow) * K;
    const float* Bip = Bw + (size_t)brow * N + col0 + bcol;

    float4 av = *(const float4*)(Aip + acol);
    float4 bv = bok ? *(const float4*)Bip : make_float4(0.f, 0.f, 0.f, 0.f);

    for (int kt = 0; kt < K / 8; kt++) {
        __syncthreads();
        As[(acol + 0) * ASPAD + arow] = av.x;
        As[(acol + 1) * ASPAD + arow] = av.y;
        As[(acol + 2) * ASPAD + arow] = av.z;
        As[(acol + 3) * ASPAD + arow] = av.w;
        u64* bd = Bs + brow * BN + bcol;
        bd[0] = dup2(bv.x); bd[1] = dup2(bv.y);
        bd[2] = dup2(bv.z); bd[3] = dup2(bv.w);
        __syncthreads();

        if (kt + 1 < K / 8) {   // prefetch next tile into regs during compute
            int k0 = (kt + 1) * 8;
            av = *(const float4*)(Aip + k0 + acol);
            bv = bok ? *(const float4*)(Bip + (size_t)k0 * N)
                     : make_float4(0.f, 0.f, 0.f, 0.f);
        }

        #pragma unroll
        for (int k = 0; k < 8; k++) {
            const ulonglong2* ar = (const ulonglong2*)(As + k * ASPAD + ty * 8);
            ulonglong2 a0 = ar[0], a1 = ar[1];
            const ulonglong2* br = (const ulonglong2*)(Bs + k * BN + tx * 8);
            ulonglong2 b0 = br[0], b1 = br[1], b2 = br[2], b3 = br[3];
            u64 am[4] = {a0.x, a0.y, a1.x, a1.y};
            u64 bn[8] = {b0.x, b0.y, b1.x, b1.y, b2.x, b2.y, b3.x, b3.y};
            #pragma unroll
            for (int mp = 0; mp < 4; mp++)
                #pragma unroll
                for (int n = 0; n < 8; n++)
                    fmaX2(acc[mp * 8 + n], am[mp], bn[n]);
        }
    }

    // epilogue: + bias, store
    const int colb = col0 + tx * 8;
    float bias8[8];
    #pragma unroll
    for (int n = 0; n < 8; n++)
        bias8[n] = (colb + n < N) ? __ldg(bias + colb + n) : 0.f;

    #pragma unroll
    for (int mp = 0; mp < 4; mp++) {
        #pragma unroll
        for (int half = 0; half < 2; half++) {
            int row = row0 + ty * 8 + mp * 2 + half;
            float* cp = C + (size_t)row * N + colb;
            float v[8];
            #pragma unroll
            for (int n = 0; n < 8; n++) {
                u64 a = acc[mp * 8 + n];
                v[n] = (half ? hi32(a) : lo32(a)) + bias8[n];
            }
            if (colb + 8 <= N) {
                *(float4*)(cp)     = make_float4(v[0], v[1], v[2], v[3]);
                *(float4*)(cp + 4) = make_float4(v[4], v[5], v[6], v[7]);
            } else {
                for (int n = 0; n < 8; n++)
                    if (colb + n < N) cp[n] = v[n];
            }
        }
    }
}

// =====================================================================
extern "C" void kernel_launch(void* const* d_in, const int* in_sizes, int n_in,
                              void* d_out, int out_size)
{
    const int*   tokens = (const int*)  d_in[0];
    const float* emb    = (const float*)d_in[1];
    const float* Wh     = (const float*)d_in[2];
    const float* Uh     = (const float*)d_in[3];
    const float* b      = (const float*)d_in[4];
    const float* fc_w   = (const float*)d_in[5];
    const float* fc_b   = (const float*)d_in[6];
    float* C = (float*)d_out;
    (void)in_sizes; (void)n_in; (void)out_size;

    cudaFuncSetAttribute(rnn_kernel,
                         cudaFuncAttributeMaxDynamicSharedMemorySize, RNN_SMEM);

    rnn_kernel<<<NCTA, RNN_THREADS, RNN_SMEM>>>(tokens, emb, Wh, Uh, b);

    dim3 grid((BATCH * SEQ) / BM, (NVOC + BN - 1) / BN);
    gemm_kernel<<<grid, 256>>>(fc_w, fc_b, C);
}

// round 7
// speedup vs baseline: 1.7797x; 1.7797x over previous
#include <cuda_runtime.h>
#include <cstdint>
#include <cstddef>

typedef unsigned long long u64;

#define BATCH 8
#define SEQ   512
#define DIM   1024
#define NVOC  32064
#define NCTA  128
#define JT    8
#define KPAD  1028
#define RNN_THREADS 256
// dynamic smem: 4 weight slices + 3 activation vectors + reduction buffer
#define RNN_SMEM ((4*JT*KPAD + 3*BATCH*DIM + RNN_THREADS) * 4)

// ---------------- scratch (device globals; no allocation allowed) ----------------
__device__ __align__(16) float g_h0[2][BATCH][DIM];            // layer0 h, parity
__device__ __align__(16) float g_h1[2][BATCH][DIM];            // layer1 h, parity
__device__ __align__(16) float g_rnn_out[BATCH * SEQ * DIM];   // 16 MB activations
__device__ unsigned g_bar_arrive;
__device__ unsigned g_bar_release;

// ---------------- packed f32x2 helpers (ptxas never emits FFMA2 from C++) --------
__device__ __forceinline__ void fmaX2(u64 &d, u64 a, u64 b) {
    asm("fma.rn.f32x2 %0, %1, %2, %0;" : "+l"(d) : "l"(a), "l"(b));
}
__device__ __forceinline__ u64 dup2(float s) {
    u64 d; asm("mov.b64 %0, {%1, %1};" : "=l"(d) : "f"(s)); return d;
}
__device__ __forceinline__ float lo32(u64 v) { return __uint_as_float((unsigned)v); }
__device__ __forceinline__ float hi32(u64 v) { return __uint_as_float((unsigned)(v >> 32)); }
__device__ __forceinline__ float sum2(u64 v) { return lo32(v) + hi32(v); }

// ---- grid barrier: monotonic generations (graph-replay safe), acq/rel (no L1 flush)
__device__ __forceinline__ void grid_barrier() {
    __syncthreads();
    if (threadIdx.x == 0) {
        unsigned ticket;
        asm volatile("atom.acq_rel.gpu.global.add.u32 %0, [%1], 1;"
                     : "=r"(ticket) : "l"(&g_bar_arrive) : "memory");
        unsigned gen = ticket / NCTA;
        if ((ticket % NCTA) == (NCTA - 1u)) {
            asm volatile("red.release.gpu.global.add.u32 [%0], 1;"
                         :: "l"(&g_bar_release) : "memory");
        } else {
            unsigned r;
            do {
                asm volatile("ld.acquire.gpu.global.u32 %0, [%1];"
                             : "=r"(r) : "l"(&g_bar_release) : "memory");
            } while (r <= gen);
        }
    }
    __syncthreads();
}

// =====================================================================
// Persistent RNN: 128 CTAs x 256 threads, CTA owns cols [j0, j0+8).
// Layer-skew pipeline: superstep s computes layer0(t=s) AND layer1(t=s-1)
// -> ONE grid barrier per superstep (513 total, was 2048).
// Thread -> (layer = tid>>7, half = (tid>>6)&1 [x-part|h-part],
//            tb = (tid>>3)&7, jj = tid&7).
// =====================================================================
__global__ void __launch_bounds__(RNN_THREADS, 1)
rnn_kernel(const int* __restrict__ tokens, const float* __restrict__ emb,
           const float* __restrict__ Wh, const float* __restrict__ Uh,
           const float* __restrict__ bias)
{
    extern __shared__ __align__(16) float smem[];
    float* sW0  = smem;
    float* sU0  = smem + 1 * JT * KPAD;
    float* sW1  = smem + 2 * JT * KPAD;
    float* sU1  = smem + 3 * JT * KPAD;
    float* sX   = smem + 4 * JT * KPAD;      // emb(t=s)        [BATCH][DIM]
    float* sH0p = sX   + BATCH * DIM;        // h0[s-1]         [BATCH][DIM]
    float* sH1p = sH0p + BATCH * DIM;        // h1[s-2]         [BATCH][DIM]
    float* sred = sH1p + BATCH * DIM;        // [RNN_THREADS]

    const int tid  = threadIdx.x;
    const int j0   = blockIdx.x * JT;
    const int jj   = tid & 7;
    const int tb   = (tid >> 3) & 7;
    const int half = (tid >> 6) & 1;
    const int lyr  = tid >> 7;

    // cache transposed weight slices: s[j][k] = W[k][j0+j], row stride KPAD
    for (int idx = tid; idx < JT * DIM; idx += RNN_THREADS) {
        int k = idx >> 3, j = idx & 7;
        sW0[j * KPAD + k] = Wh[k * DIM + j0 + j];
        sU0[j * KPAD + k] = Uh[k * DIM + j0 + j];
        sW1[j * KPAD + k] = Wh[DIM * DIM + k * DIM + j0 + j];
        sU1[j * KPAD + k] = Uh[DIM * DIM + k * DIM + j0 + j];
    }
    // re-zero both parities of both hidden states every launch (replay-dirty)
    if (tid < 64) {
        int zb = tid >> 3, zj = j0 + (tid & 7);
        g_h0[0][zb][zj] = 0.f; g_h0[1][zb][zj] = 0.f;
        g_h1[0][zb][zj] = 0.f; g_h1[1][zb][zj] = 0.f;
    }
    const float bval = bias[lyr * DIM + j0 + jj];

    // fixed per-thread act/weight pointers (smem buffers are re-filled in place)
    const float* act;
    const float* wrow;
    if (lyr == 0) { act = half ? sH0p : sX;   wrow = half ? sU0 : sW0; }
    else          { act = half ? sH1p : sH0p; wrow = half ? sU1 : sW1; }
    act  += tb * DIM;
    wrow += jj * KPAD;

    grid_barrier();   // weights + zeroed states visible everywhere

    for (int s = 0; s <= SEQ; s++) {
        const int pr = (s + 1) & 1;   // parity holding h0[s-1] / h1[s-2]

        // ---------- stage 3 activation vectors ----------
        {
            float4* dX  = (float4*)sX;
            float4* dH0 = (float4*)sH0p;
            float4* dH1 = (float4*)sH1p;
            const float4* h0s = (const float4*)&g_h0[pr][0][0];
            const float4* h1s = (const float4*)&g_h1[pr][0][0];
            for (int v = tid; v < (BATCH * DIM / 4); v += RNN_THREADS) {
                dH0[v] = __ldcg(h0s + v);          // bypass stale L1
                dH1[v] = __ldcg(h1s + v);
                float4 x = make_float4(0.f, 0.f, 0.f, 0.f);
                if (s < SEQ) {
                    int bb = v >> 8;               // 256 float4 per batch row
                    int kk = (v & 255) << 2;
                    int tk = __ldg(tokens + bb * SEQ + s);
                    if (tk != 0) x = __ldg((const float4*)(emb + (size_t)tk * DIM + kk));
                }
                dX[v] = x;
            }
        }
        __syncthreads();

        // ---------- 1024-long dot (this thread's half of one output) ----------
        {
            const ulonglong2* xp = (const ulonglong2*)act;
            const ulonglong2* wp = (const ulonglong2*)wrow;
            u64 a0 = 0ull, a1 = 0ull, a2 = 0ull, a3 = 0ull;
            #pragma unroll 8
            for (int i = 0; i < 256; i += 2) {
                ulonglong2 xv = xp[i],     wv = wp[i];
                fmaX2(a0, xv.x, wv.x);
                fmaX2(a1, xv.y, wv.y);
                ulonglong2 xw = xp[i + 1], ww = wp[i + 1];
                fmaX2(a2, xw.x, ww.x);
                fmaX2(a3, xw.y, ww.y);
            }
            sred[tid] = sum2(a0) + sum2(a1) + sum2(a2) + sum2(a3);
        }
        __syncthreads();

        if (half == 0) {
            float v = sred[tid] + sred[tid ^ 64] + bval;
            float hv = tanhf(v);
            if (lyr == 0) {
                if (s < SEQ) g_h0[s & 1][tb][j0 + jj] = hv;
            } else {
                if (s >= 1) {
                    g_h1[s & 1][tb][j0 + jj] = hv;
                    g_rnn_out[(size_t)(tb * SEQ + (s - 1)) * DIM + j0 + jj] = hv;
                }
            }
        }
        grid_barrier();
    }
}

// =====================================================================
// Projection: C[4096,32064] = g_rnn_out[4096,1024] @ fc_w[1024,32064] + fc_b
// 128x128x8 tiles, 8x8/thread, fma.rn.f32x2. B kept as plain floats in
// smem (dup2 into regs per k on the ALU pipe) -> half the LDS traffic of
// round 6. Double-buffered smem: one __syncthreads per k-tile.
// =====================================================================
#define BM 128
#define BN 128
#define ASPAD 132   // 528-byte row stride, 16B-aligned, conflict-free transpose

__global__ void __launch_bounds__(256)
gemm_kernel(const float* __restrict__ Bw, const float* __restrict__ bias,
            float* __restrict__ C)
{
    const int N = NVOC, K = DIM;
    const float* __restrict__ A = g_rnn_out;

    __shared__ __align__(16) float As[2][8 * ASPAD];   // [buf][k][m] transposed
    __shared__ __align__(16) float Bs[2][8 * BN];      // [buf][k][n]

    const int tid = threadIdx.x;
    const int tx = tid & 15, ty = tid >> 4;
    const int row0 = blockIdx.x * BM;                  // M fast -> A L2-resident
    const int col0 = blockIdx.y * BN;

    const int arow = tid >> 1, acol = (tid & 1) << 2;
    const int brow = tid >> 5, bcol = (tid & 31) << 2;
    const bool bok = (col0 + bcol) < N;                // N%4==0: f4 all-or-nothing

    u64 acc[32];
    #pragma unroll
    for (int i = 0; i < 32; i++) acc[i] = 0ull;

    const float* Aip = A + (size_t)(row0 + arow) * K;
    const float* Bip = Bw + (size_t)brow * N + col0 + bcol;

    // preload tile 0 and stage into buffer 0
    float4 av = *(const float4*)(Aip + acol);
    float4 bv = bok ? *(const float4*)Bip : make_float4(0.f, 0.f, 0.f, 0.f);
    As[0][(acol + 0) * ASPAD + arow] = av.x;
    As[0][(acol + 1) * ASPAD + arow] = av.y;
    As[0][(acol + 2) * ASPAD + arow] = av.z;
    As[0][(acol + 3) * ASPAD + arow] = av.w;
    *(float4*)(Bs[0] + brow * BN + bcol) = bv;
    __syncthreads();

    const int KT = K / 8;
    for (int kt = 0; kt < KT; kt++) {
        const int cur = kt & 1;
        const bool has_next = (kt + 1) < KT;

        if (has_next) {                       // prefetch next tile into regs
            int k0 = (kt + 1) * 8;
            av = *(const float4*)(Aip + k0 + acol);
            bv = bok ? *(const float4*)(Bip + (size_t)k0 * N)
                     : make_float4(0.f, 0.f, 0.f, 0.f);
        }

        #pragma unroll
        for (int k = 0; k < 8; k++) {
            const ulonglong2* ar = (const ulonglong2*)(As[cur] + k * ASPAD + ty * 8);
            ulonglong2 a0 = ar[0], a1 = ar[1];
            u64 am[4] = {a0.x, a0.y, a1.x, a1.y};
            const float4 f0 = *(const float4*)(Bs[cur] + k * BN + tx * 8);
            const float4 f1 = *(const float4*)(Bs[cur] + k * BN + tx * 8 + 4);
            u64 bn[8] = {dup2(f0.x), dup2(f0.y), dup2(f0.z), dup2(f0.w),
                         dup2(f1.x), dup2(f1.y), dup2(f1.z), dup2(f1.w)};
            #pragma unroll
            for (int mp = 0; mp < 4; mp++)
                #pragma unroll
                for (int n = 0; n < 8; n++)
                    fmaX2(acc[mp * 8 + n], am[mp], bn[n]);
        }

        if (has_next) {                       // stage prefetched tile -> other buf
            const int nxt = cur ^ 1;
            As[nxt][(acol + 0) * ASPAD + arow] = av.x;
            As[nxt][(acol + 1) * ASPAD + arow] = av.y;
            As[nxt][(acol + 2) * ASPAD + arow] = av.z;
            As[nxt][(acol + 3) * ASPAD + arow] = av.w;
            *(float4*)(Bs[nxt] + brow * BN + bcol) = bv;
        }
        __syncthreads();
    }

    // epilogue: + bias, store
    const int colb = col0 + tx * 8;
    float bias8[8];
    #pragma unroll
    for (int n = 0; n < 8; n++)
        bias8[n] = (colb + n < N) ? __ldg(bias + colb + n) : 0.f;

    #pragma unroll
    for (int mp = 0; mp < 4; mp++) {
        #pragma unroll
        for (int hf = 0; hf < 2; hf++) {
            int row = row0 + ty * 8 + mp * 2 + hf;
            float* cp = C + (size_t)row * N + colb;
            float v[8];
            #pragma unroll
            for (int n = 0; n < 8; n++) {
                u64 a = acc[mp * 8 + n];
                v[n] = (hf ? hi32(a) : lo32(a)) + bias8[n];
            }
            if (colb + 8 <= N) {
                *(float4*)(cp)     = make_float4(v[0], v[1], v[2], v[3]);
                *(float4*)(cp + 4) = make_float4(v[4], v[5], v[6], v[7]);
            } else {
                for (int n = 0; n < 8; n++)
                    if (colb + n < N) cp[n] = v[n];
            }
        }
    }
}

// =====================================================================
extern "C" void kernel_launch(void* const* d_in, const int* in_sizes, int n_in,
                              void* d_out, int out_size)
{
    const int*   tokens = (const int*)  d_in[0];
    const float* emb    = (const float*)d_in[1];
    const float* Wh     = (const float*)d_in[2];
    const float* Uh     = (const float*)d_in[3];
    const float* b      = (const float*)d_in[4];
    const float* fc_w   = (const float*)d_in[5];
    const float* fc_b   = (const float*)d_in[6];
    float* C = (float*)d_out;
    (void)in_sizes; (void)n_in; (void)out_size;

    cudaFuncSetAttribute(rnn_kernel,
                         cudaFuncAttributeMaxDynamicSharedMemorySize, RNN_SMEM);

    rnn_kernel<<<NCTA, RNN_THREADS, RNN_SMEM>>>(tokens, emb, Wh, Uh, b);

    dim3 grid((BATCH * SEQ) / BM, (NVOC + BN - 1) / BN);
    gemm_kernel<<<grid, 256>>>(fc_w, fc_b, C);
}

// round 12
// speedup vs baseline: 2.7375x; 1.5382x over previous
#include <cuda_runtime.h>
#include <cuda_bf16.h>
#include <cstdint>
#include <cstddef>

typedef unsigned long long u64;
typedef unsigned int u32;

#define BATCH 8
#define SEQ   512
#define DIM   1024
#define NVOC  32064
#define NVOC_PAD 32128          // 251 * 128
#define NCTA  128
#define JT    8
#define KPAD  1028
#define RNN_THREADS 256
#define RNN_SMEM ((4*JT*KPAD + 3*BATCH*DIM + RNN_THREADS) * 4)

// ---------------- scratch (device globals; no allocation allowed) ----------------
__device__ __align__(16) float g_h0[2][BATCH][DIM];
__device__ __align__(16) float g_h1[2][BATCH][DIM];
__device__ __align__(16) float g_rnn_out[BATCH * SEQ * DIM];      // 16 MB
__device__ __align__(16) __nv_bfloat16 g_Ahi[BATCH * SEQ * DIM];  // 8 MB
__device__ __align__(16) __nv_bfloat16 g_Alo[BATCH * SEQ * DIM];  // 8 MB
__device__ __align__(16) __nv_bfloat16 g_WhiT[(size_t)NVOC_PAD * DIM]; // 66 MB, pad rows stay 0
__device__ __align__(16) __nv_bfloat16 g_WloT[(size_t)NVOC_PAD * DIM]; // 66 MB
__device__ unsigned g_bar_arrive;
__device__ unsigned g_bar_release;

// ---------------- packed f32x2 helpers ----------------
__device__ __forceinline__ void fmaX2(u64 &d, u64 a, u64 b) {
    asm("fma.rn.f32x2 %0, %1, %2, %0;" : "+l"(d) : "l"(a), "l"(b));
}
__device__ __forceinline__ float lo32(u64 v) { return __uint_as_float((unsigned)v); }
__device__ __forceinline__ float hi32(u64 v) { return __uint_as_float((unsigned)(v >> 32)); }
__device__ __forceinline__ float sum2(u64 v) { return lo32(v) + hi32(v); }

__device__ __forceinline__ u32 smem_u32(const void* p) {
    u32 a;
    asm("{ .reg .u64 t; cvta.to.shared.u64 t, %1; cvt.u32.u64 %0, t; }" : "=r"(a) : "l"(p));
    return a;
}

// ---------------- HMMA helpers (valid PTX at base sm_103) ----------------
__device__ __forceinline__ void ldsm4(u32* r, u32 addr) {
    asm volatile("ldmatrix.sync.aligned.m8n8.x4.shared.b16 {%0,%1,%2,%3}, [%4];"
        : "=r"(r[0]), "=r"(r[1]), "=r"(r[2]), "=r"(r[3]) : "r"(addr));
}
__device__ __forceinline__ void mma16816(float* c, const u32* a, const u32* b) {
    asm volatile(
        "mma.sync.aligned.m16n8k16.row.col.f32.bf16.bf16.f32 "
        "{%0,%1,%2,%3}, {%4,%5,%6,%7}, {%8,%9}, {%0,%1,%2,%3};"
        : "+f"(c[0]), "+f"(c[1]), "+f"(c[2]), "+f"(c[3])
        : "r"(a[0]), "r"(a[1]), "r"(a[2]), "r"(a[3]), "r"(b[0]), "r"(b[1]));
}
#define CP_ASYNC16(smem, gmem) \
    asm volatile("cp.async.cg.shared.global [%0], [%1], 16;" :: "r"(smem), "l"(gmem))
#define CP_COMMIT() asm volatile("cp.async.commit_group;" ::: "memory")
#define CP_WAIT(n)  asm volatile("cp.async.wait_group %0;" :: "n"(n) : "memory")

// ---- grid barrier: monotonic generations (graph-replay safe), acq/rel ----
__device__ __forceinline__ void grid_barrier() {
    __syncthreads();
    if (threadIdx.x == 0) {
        unsigned ticket;
        asm volatile("atom.acq_rel.gpu.global.add.u32 %0, [%1], 1;"
                     : "=r"(ticket) : "l"(&g_bar_arrive) : "memory");
        unsigned gen = ticket / NCTA;
        if ((ticket % NCTA) == (NCTA - 1u)) {
            asm volatile("red.release.gpu.global.add.u32 [%0], 1;"
                         :: "l"(&g_bar_release) : "memory");
        } else {
            unsigned r;
            do {
                asm volatile("ld.acquire.gpu.global.u32 %0, [%1];"
                             : "=r"(r) : "l"(&g_bar_release) : "memory");
            } while (r <= gen);
        }
    }
    __syncthreads();
}

// =====================================================================
// Persistent RNN (layer-skew, 1 barrier/superstep).
// =====================================================================
__global__ void __launch_bounds__(RNN_THREADS, 1)
rnn_kernel(const int* __restrict__ tokens, const float* __restrict__ emb,
           const float* __restrict__ Wh, const float* __restrict__ Uh,
           const float* __restrict__ bias)
{
    extern __shared__ __align__(16) float smem[];
    float* sW0  = smem;
    float* sU0  = smem + 1 * JT * KPAD;
    float* sW1  = smem + 2 * JT * KPAD;
    float* sU1  = smem + 3 * JT * KPAD;
    float* sX   = smem + 4 * JT * KPAD;
    float* sH0p = sX   + BATCH * DIM;
    float* sH1p = sH0p + BATCH * DIM;
    float* sred = sH1p + BATCH * DIM;

    const int tid  = threadIdx.x;
    const int j0   = blockIdx.x * JT;
    const int jj   = tid & 7;
    const int tb   = (tid >> 3) & 7;
    const int half = (tid >> 6) & 1;
    const int lyr  = tid >> 7;

    for (int idx = tid; idx < JT * DIM; idx += RNN_THREADS) {
        int k = idx >> 3, j = idx & 7;
        sW0[j * KPAD + k] = Wh[k * DIM + j0 + j];
        sU0[j * KPAD + k] = Uh[k * DIM + j0 + j];
        sW1[j * KPAD + k] = Wh[DIM * DIM + k * DIM + j0 + j];
        sU1[j * KPAD + k] = Uh[DIM * DIM + k * DIM + j0 + j];
    }
    if (tid < 64) {
        int zb = tid >> 3, zj = j0 + (tid & 7);
        g_h0[0][zb][zj] = 0.f; g_h0[1][zb][zj] = 0.f;
        g_h1[0][zb][zj] = 0.f; g_h1[1][zb][zj] = 0.f;
    }
    const float bval = bias[lyr * DIM + j0 + jj];

    const float* act;
    const float* wrow;
    if (lyr == 0) { act = half ? sH0p : sX;   wrow = half ? sU0 : sW0; }
    else          { act = half ? sH1p : sH0p; wrow = half ? sU1 : sW1; }
    act  += tb * DIM;
    wrow += jj * KPAD;

    {   // prefetch X[0]
        float4* dX = (float4*)sX;
        for (int j = 0; j < 8; j++) {
            int v = tid + j * 256;
            int bb = v >> 8, kk = (v & 255) << 2;
            int tk = __ldg(tokens + bb * SEQ + 0);
            float4 x = make_float4(0.f, 0.f, 0.f, 0.f);
            if (tk != 0) x = __ldg((const float4*)(emb + (size_t)tk * DIM + kk));
            dX[v] = x;
        }
    }
    grid_barrier();

    for (int s = 0; s <= SEQ; s++) {
        const int pr = (s + 1) & 1;

        {   // stage hidden vectors: 16 batched ldcg -> regs -> STS
            const float4* h0s = (const float4*)&g_h0[pr][0][0];
            const float4* h1s = (const float4*)&g_h1[pr][0][0];
            float4 r0[8], r1[8];
            #pragma unroll
            for (int j = 0; j < 8; j++) {
                r0[j] = __ldcg(h0s + tid + j * 256);
                r1[j] = __ldcg(h1s + tid + j * 256);
            }
            float4* d0 = (float4*)sH0p;
            float4* d1 = (float4*)sH1p;
            #pragma unroll
            for (int j = 0; j < 8; j++) {
                d0[tid + j * 256] = r0[j];
                d1[tid + j * 256] = r1[j];
            }
        }
        __syncthreads();

        {   // 1024-long dot: this thread's half of one output
            const ulonglong2* xp = (const ulonglong2*)act;
            const ulonglong2* wp = (const ulonglong2*)wrow;
            u64 a0 = 0ull, a1 = 0ull, a2 = 0ull, a3 = 0ull;
            #pragma unroll 8
            for (int i = 0; i < 256; i += 2) {
                ulonglong2 xv = xp[i],     wv = wp[i];
                fmaX2(a0, xv.x, wv.x);
                fmaX2(a1, xv.y, wv.y);
                ulonglong2 xw = xp[i + 1], ww = wp[i + 1];
                fmaX2(a2, xw.x, ww.x);
                fmaX2(a3, xw.y, ww.y);
            }
            sred[tid] = sum2(a0) + sum2(a1) + sum2(a2) + sum2(a3);
        }
        __syncthreads();

        if (half == 0) {
            float v = sred[tid] + sred[tid ^ 64] + bval;
            float hv = tanhf(v);
            if (lyr == 0) {
                if (s < SEQ) g_h0[s & 1][tb][j0 + jj] = hv;
            } else if (s >= 1) {
                g_h1[s & 1][tb][j0 + jj] = hv;
                g_rnn_out[(size_t)(tb * SEQ + (s - 1)) * DIM + j0 + jj] = hv;
            }
        }

        // prefetch X[s+1] BEFORE the barrier (overlaps barrier wait)
        if (s + 1 < SEQ) {
            float4* dX = (float4*)sX;
            for (int j = 0; j < 8; j++) {
                int v = tid + j * 256;
                int bb = v >> 8, kk = (v & 255) << 2;
                int tk = __ldg(tokens + bb * SEQ + (s + 1));
                float4 x = make_float4(0.f, 0.f, 0.f, 0.f);
                if (tk != 0) x = __ldg((const float4*)(emb + (size_t)tk * DIM + kk));
                dX[v] = x;
            }
        }
        grid_barrier();
    }
}

// =====================================================================
// Convert A: g_rnn_out fp32 -> hi/lo bf16 (same layout, K-major)
// =====================================================================
__global__ void __launch_bounds__(256)
convA_kernel()
{
    int v = blockIdx.x * 256 + threadIdx.x;           // float4 index
    const float4* src = (const float4*)g_rnn_out;
    float4 x = src[v];
    __nv_bfloat16 hi[4], lo[4];
    float xs[4] = {x.x, x.y, x.z, x.w};
    #pragma unroll
    for (int i = 0; i < 4; i++) {
        hi[i] = __float2bfloat16(xs[i]);
        lo[i] = __float2bfloat16(xs[i] - __bfloat162float(hi[i]));
    }
    *(uint2*)(g_Ahi + (size_t)v * 4) = *(uint2*)hi;
    *(uint2*)(g_Alo + (size_t)v * 4) = *(uint2*)lo;
}

// =====================================================================
// Convert + transpose W: fc_w[k][n] fp32 -> g_WhiT/g_WloT[n][k] bf16
// =====================================================================
__global__ void __launch_bounds__(256)
convW_kernel(const float* __restrict__ W)
{
    __shared__ float s[32][36];
    const int n0 = blockIdx.x * 32;
    const int k0 = blockIdx.y * 32;
    const int tid = threadIdx.x;
    const int ty = tid >> 3;
    const int tx = (tid & 7) << 2;

    float4 v = *(const float4*)(W + (size_t)(k0 + ty) * NVOC + n0 + tx);
    s[ty][tx + 0] = v.x; s[ty][tx + 1] = v.y;
    s[ty][tx + 2] = v.z; s[ty][tx + 3] = v.w;
    __syncthreads();

    const int r  = tid >> 3;
    const int c4 = (tid & 7) << 2;
    __nv_bfloat16 hi[4], lo[4];
    #pragma unroll
    for (int j = 0; j < 4; j++) {
        float x = s[c4 + j][r];
        hi[j] = __float2bfloat16(x);
        lo[j] = __float2bfloat16(x - __bfloat162float(hi[j]));
    }
    size_t off = (size_t)(n0 + r) * DIM + k0 + c4;
    *(uint2*)(g_WhiT + off) = *(uint2*)hi;
    *(uint2*)(g_WloT + off) = *(uint2*)lo;
}

// =====================================================================
// HMMA projection: C[4096,32064] = A @ W^T + bias, split-bf16 (3 products).
// CTA 128x128xK32, 8 warps (2x4), warp tile 64x32 = 4x4 m16n8k16 frags.
// cp.async double-buffered smem; 80B row stride (conflict-free ldmatrix,
// 16B-aligned). Grid M-fastest: A L2-resident, W streams once.
// =====================================================================
#define GSTRIDE 80                       // bytes per 32-bf16 row in smem
#define GTILE   (128 * GSTRIDE)          // 10240 B: one matrix-half tile
#define OFF_AHI 0
#define OFF_ALO (1 * GTILE)
#define OFF_BHI (2 * GTILE)
#define OFF_BLO (3 * GTILE)
#define STAGE_BYTES (4 * GTILE)          // 40960
#define GEMM_SMEM (2 * STAGE_BYTES)      // 81920
#define NKT (DIM / 32)                   // 32 k-tiles

__global__ void __launch_bounds__(256, 1)
gemm_hmma_kernel(const float* __restrict__ bias, float* __restrict__ C)
{
    extern __shared__ __align__(16) char smc[];
    const u32 sb = smem_u32(smc);
    const int tid = threadIdx.x;
    const int wid = tid >> 5;
    const int lane = tid & 31;
    const int wm = wid & 1;              // warp row (2)
    const int wn = wid >> 1;             // warp col (4)
    const int row0 = blockIdx.x * 128;   // M fast
    const int col0 = blockIdx.y * 128;

    // cp.async source/dest lane mapping: chunk c -> row c>>2, 16B-vec c&3
    const int c0r = (tid) >> 2,        c0v = (tid) & 3;
    const int c1r = (tid + 256) >> 2,  c1v = (tid + 256) & 3;
    const u32 s0 = (u32)(c0r * GSTRIDE + c0v * 16);
    const u32 s1 = (u32)(c1r * GSTRIDE + c1v * 16);
    const size_t ga0 = (size_t)(row0 + c0r) * DIM + c0v * 8;
    const size_t ga1 = (size_t)(row0 + c1r) * DIM + c1v * 8;
    const size_t gb0 = (size_t)(col0 + c0r) * DIM + c0v * 8;
    const size_t gb1 = (size_t)(col0 + c1r) * DIM + c1v * 8;

    // ldmatrix per-lane offsets
    const u32 aRowOff = (u32)((wm * 64 + (lane & 7) + ((lane >> 3) & 1) * 8) * GSTRIDE
                              + (lane >> 4) * 16);
    const u32 bRowOff = (u32)((wn * 32 + (lane & 7) + (lane >> 4) * 8) * GSTRIDE
                              + ((lane >> 3) & 1) * 16);

    float acc[4][4][4];
    #pragma unroll
    for (int i = 0; i < 4; i++)
        #pragma unroll
        for (int j = 0; j < 4; j++)
            #pragma unroll
            for (int q = 0; q < 4; q++) acc[i][j][q] = 0.f;

    // ---- prologue: stage 0 ----
    {
        const int kc = 0;
        u32 st = sb;
        CP_ASYNC16(st + OFF_AHI + s0, g_Ahi + ga0 + kc);
        CP_ASYNC16(st + OFF_AHI + s1, g_Ahi + ga1 + kc);
        CP_ASYNC16(st + OFF_ALO + s0, g_Alo + ga0 + kc);
        CP_ASYNC16(st + OFF_ALO + s1, g_Alo + ga1 + kc);
        CP_ASYNC16(st + OFF_BHI + s0, g_WhiT + gb0 + kc);
        CP_ASYNC16(st + OFF_BHI + s1, g_WhiT + gb1 + kc);
        CP_ASYNC16(st + OFF_BLO + s0, g_WloT + gb0 + kc);
        CP_ASYNC16(st + OFF_BLO + s1, g_WloT + gb1 + kc);
        CP_COMMIT();
    }

    for (int kt = 0; kt < NKT; kt++) {
        if (kt + 1 < NKT) {
            const int kc = (kt + 1) * 32;
            u32 st = sb + ((kt + 1) & 1) * STAGE_BYTES;
            CP_ASYNC16(st + OFF_AHI + s0, g_Ahi + ga0 + kc);
            CP_ASYNC16(st + OFF_AHI + s1, g_Ahi + ga1 + kc);
            CP_ASYNC16(st + OFF_ALO + s0, g_Alo + ga0 + kc);
            CP_ASYNC16(st + OFF_ALO + s1, g_Alo + ga1 + kc);
            CP_ASYNC16(st + OFF_BHI + s0, g_WhiT + gb0 + kc);
            CP_ASYNC16(st + OFF_BHI + s1, g_WhiT + gb1 + kc);
            CP_ASYNC16(st + OFF_BLO + s0, g_WloT + gb0 + kc);
            CP_ASYNC16(st + OFF_BLO + s1, g_WloT + gb1 + kc);
            CP_COMMIT();
            CP_WAIT(1);
        } else {
            CP_WAIT(0);
        }
        __syncthreads();

        const u32 st = sb + (kt & 1) * STAGE_BYTES;
        const u32 aHi = st + OFF_AHI + aRowOff;
        const u32 aLo = st + OFF_ALO + aRowOff;
        const u32 bHi = st + OFF_BHI + bRowOff;
        const u32 bLo = st + OFF_BLO + bRowOff;

        #pragma unroll
        for (int ks = 0; ks < 2; ks++) {
            u32 ah[4][4], al[4][4], bh[2][4], bl[2][4];
            #pragma unroll
            for (int mt = 0; mt < 4; mt++) {
                ldsm4(ah[mt], aHi + mt * (16 * GSTRIDE) + ks * 32);
                ldsm4(al[mt], aLo + mt * (16 * GSTRIDE) + ks * 32);
            }
            #pragma unroll
            for (int g = 0; g < 2; g++) {
                ldsm4(bh[g], bHi + g * (16 * GSTRIDE) + ks * 32);
                ldsm4(bl[g], bLo + g * (16 * GSTRIDE) + ks * 32);
            }
            #pragma unroll
            for (int mt = 0; mt < 4; mt++)
                #pragma unroll
                for (int nt = 0; nt < 4; nt++) {
                    float* c = acc[mt][nt];
                    const u32* bhp = &bh[nt >> 1][(nt & 1) * 2];
                    const u32* blp = &bl[nt >> 1][(nt & 1) * 2];
                    mma16816(c, ah[mt], bhp);
                    mma16816(c, ah[mt], blp);
                    mma16816(c, al[mt], bhp);
                }
        }
        __syncthreads();
    }

    // ---- epilogue: + bias, store (skip n >= NVOC pad cols) ----
    #pragma unroll
    for (int nt = 0; nt < 4; nt++) {
        const int n = col0 + wn * 32 + nt * 8 + (lane & 3) * 2;
        if (n >= NVOC) continue;
        const float b0 = __ldg(bias + n);
        const float b1 = __ldg(bias + n + 1);
        #pragma unroll
        for (int mt = 0; mt < 4; mt++) {
            const int m = row0 + wm * 64 + mt * 16 + (lane >> 2);
            float* cp0 = C + (size_t)m * NVOC + n;
            float* cp1 = C + (size_t)(m + 8) * NVOC + n;
            *(float2*)cp0 = make_float2(acc[mt][nt][0] + b0, acc[mt][nt][1] + b1);
            *(float2*)cp1 = make_float2(acc[mt][nt][2] + b0, acc[mt][nt][3] + b1);
        }
    }
}

// =====================================================================
extern "C" void kernel_launch(void* const* d_in, const int* in_sizes, int n_in,
                              void* d_out, int out_size)
{
    const int*   tokens = (const int*)  d_in[0];
    const float* emb    = (const float*)d_in[1];
    const float* Wh     = (const float*)d_in[2];
    const float* Uh     = (const float*)d_in[3];
    const float* b      = (const float*)d_in[4];
    const float* fc_w   = (const float*)d_in[5];
    const float* fc_b   = (const float*)d_in[6];
    float* C = (float*)d_out;
    (void)in_sizes; (void)n_in; (void)out_size;

    cudaFuncSetAttribute(rnn_kernel,
                         cudaFuncAttributeMaxDynamicSharedMemorySize, RNN_SMEM);
    cudaFuncSetAttribute(gemm_hmma_kernel,
                         cudaFuncAttributeMaxDynamicSharedMemorySize, GEMM_SMEM);

    // W conversion is RNN-independent; A conversion needs g_rnn_out.
    dim3 wgrid(NVOC / 32, DIM / 32);
    convW_kernel<<<wgrid, 256>>>(fc_w);

    rnn_kernel<<<NCTA, RNN_THREADS, RNN_SMEM>>>(tokens, emb, Wh, Uh, b);

    convA_kernel<<<(BATCH * SEQ * DIM / 4) / 256, 256>>>();

    dim3 ggrid((BATCH * SEQ) / 128, NVOC_PAD / 128);
    gemm_hmma_kernel<<<ggrid, 256, GEMM_SMEM>>>(fc_b, C);
}

// round 14
// speedup vs baseline: 4.4371x; 1.6208x over previous
#include <cuda_runtime.h>
#include <cuda_bf16.h>
#include <cstdint>
#include <cstddef>

typedef unsigned long long u64;
typedef unsigned int u32;

#define BATCH 8
#define SEQ   512
#define DIM   1024
#define NVOC  32064
#define NVOC_PAD 32128          // 251 * 128
#define NCTA  128
#define JT    8
#define RNN_THREADS 256

// padded act layout: 8 chunks of 128 floats, each chunk padded to 528 B
#define CHUNK_B 528
#define ROW_B   (8 * CHUNK_B)               // 4224 B per batch row
#define ACT_F   (BATCH * ROW_B / 4)         // 8448 floats per act buffer
#define RNN_SMEM ((3 * ACT_F + RNN_THREADS * 8) * 4)   // 3 acts + sred

// ---------------- scratch (device globals; no allocation allowed) ----------------
__device__ __align__(16) float g_h0[2][BATCH][DIM];
__device__ __align__(16) float g_h1[2][BATCH][DIM];
__device__ __align__(16) float g_rnn_out[BATCH * SEQ * DIM];      // 16 MB
__device__ __align__(16) __nv_bfloat16 g_Ahi[BATCH * SEQ * DIM];  // 8 MB
__device__ __align__(16) __nv_bfloat16 g_Alo[BATCH * SEQ * DIM];  // 8 MB
__device__ __align__(16) __nv_bfloat16 g_WhiT[(size_t)NVOC_PAD * DIM]; // 66 MB, pad rows stay 0
__device__ __align__(16) __nv_bfloat16 g_WloT[(size_t)NVOC_PAD * DIM]; // 66 MB
__device__ unsigned g_bar_arrive;
__device__ unsigned g_bar_release;

// ---------------- packed f32x2 helpers ----------------
__device__ __forceinline__ void fmaX2(u64 &d, u64 a, u64 b) {
    asm("fma.rn.f32x2 %0, %1, %2, %0;" : "+l"(d) : "l"(a), "l"(b));
}
__device__ __forceinline__ u64 pack2(float lo, float hi) {
    u64 d; asm("mov.b64 %0, {%1, %2};" : "=l"(d) : "f"(lo), "f"(hi)); return d;
}
__device__ __forceinline__ float lo32(u64 v) { return __uint_as_float((unsigned)v); }
__device__ __forceinline__ float hi32(u64 v) { return __uint_as_float((unsigned)(v >> 32)); }
__device__ __forceinline__ float sum2(u64 v) { return lo32(v) + hi32(v); }

__device__ __forceinline__ u32 smem_u32(const void* p) {
    u32 a;
    asm("{ .reg .u64 t; cvta.to.shared.u64 t, %1; cvt.u32.u64 %0, t; }" : "=r"(a) : "l"(p));
    return a;
}

// ---------------- HMMA helpers (valid PTX at base sm_103) ----------------
__device__ __forceinline__ void ldsm4(u32* r, u32 addr) {
    asm volatile("ldmatrix.sync.aligned.m8n8.x4.shared.b16 {%0,%1,%2,%3}, [%4];"
        : "=r"(r[0]), "=r"(r[1]), "=r"(r[2]), "=r"(r[3]) : "r"(addr));
}
__device__ __forceinline__ void mma16816(float* c, const u32* a, const u32* b) {
    asm volatile(
        "mma.sync.aligned.m16n8k16.row.col.f32.bf16.bf16.f32 "
        "{%0,%1,%2,%3}, {%4,%5,%6,%7}, {%8,%9}, {%0,%1,%2,%3};"
        : "+f"(c[0]), "+f"(c[1]), "+f"(c[2]), "+f"(c[3])
        : "r"(a[0]), "r"(a[1]), "r"(a[2]), "r"(a[3]), "r"(b[0]), "r"(b[1]));
}
#define CP_ASYNC16(smem, gmem) \
    asm volatile("cp.async.cg.shared.global [%0], [%1], 16;" :: "r"(smem), "l"(gmem))
#define CP_COMMIT() asm volatile("cp.async.commit_group;" ::: "memory")
#define CP_WAIT(n)  asm volatile("cp.async.wait_group %0;" :: "n"(n) : "memory")

// ---- grid barrier: monotonic generations (graph-replay safe), acq/rel ----
__device__ __forceinline__ void grid_barrier() {
    __syncthreads();
    if (threadIdx.x == 0) {
        unsigned ticket;
        asm volatile("atom.acq_rel.gpu.global.add.u32 %0, [%1], 1;"
                     : "=r"(ticket) : "l"(&g_bar_arrive) : "memory");
        unsigned gen = ticket / NCTA;
        if ((ticket % NCTA) == (NCTA - 1u)) {
            asm volatile("red.release.gpu.global.add.u32 [%0], 1;"
                         :: "l"(&g_bar_release) : "memory");
        } else {
            unsigned r;
            do {
                asm volatile("ld.acquire.gpu.global.u32 %0, [%1];"
                             : "=r"(r) : "l"(&g_bar_release) : "memory");
            } while (r <= gen);
        }
    }
    __syncthreads();
}

// =====================================================================
// Persistent RNN, register-resident weights.
// 128 CTAs x 256 thr. thread -> pl = tid>>6 (0:x.W0 1:h.U0 2:h0.W1 3:h1.U1),
// kc = (tid>>3)&7 (128-float K-chunk), jj = tid&7 (output column).
// Each thread: 64 packed-u64 weight regs; per superstep loops 8 batches
// over its act chunk (smem, 528B-padded stride -> distinct bank groups
// for the 4 kc values in a warp). Partials reduced via sred.
// =====================================================================
__global__ void __launch_bounds__(RNN_THREADS, 1)
rnn_kernel(const int* __restrict__ tokens, const float* __restrict__ emb,
           const float* __restrict__ Wh, const float* __restrict__ Uh,
           const float* __restrict__ bias)
{
    extern __shared__ __align__(16) float smem[];
    float* sX   = smem;
    float* sH0  = smem + ACT_F;
    float* sH1  = smem + 2 * ACT_F;
    float* sred = smem + 3 * ACT_F;          // [256][8]

    const int tid = threadIdx.x;
    const int j0  = blockIdx.x * JT;
    const int jj  = tid & 7;
    const int kc  = (tid >> 3) & 7;
    const int pl  = tid >> 6;

    // ---- load this thread's 128-float weight chunk into 64 u64 regs ----
    const float* M = Wh;
    if      (pl == 1) M = Uh;
    else if (pl == 2) M = Wh + DIM * DIM;
    else if (pl == 3) M = Uh + DIM * DIM;
    const int col = j0 + jj;
    const int kbase = kc * 128;
    u64 w[64];
    #pragma unroll
    for (int t = 0; t < 64; t++) {
        float w0 = __ldg(M + (size_t)(kbase + 2 * t) * DIM + col);
        float w1 = __ldg(M + (size_t)(kbase + 2 * t + 1) * DIM + col);
        w[t] = pack2(w0, w1);
    }

    // re-zero hidden states (replay-dirty)
    if (tid < 64) {
        int zb = tid >> 3, zj = j0 + (tid & 7);
        g_h0[0][zb][zj] = 0.f; g_h0[1][zb][zj] = 0.f;
        g_h1[0][zb][zj] = 0.f; g_h1[1][zb][zj] = 0.f;
    }

    // output-thread params (tid < 128): o -> (olyr, ojj, ob)
    const int olyr = (tid >> 6) & 1;
    const int ojj  = (tid >> 3) & 7;
    const int ob   = tid & 7;
    const float bo = (tid < 128) ? bias[olyr * DIM + j0 + ojj] : 0.f;

    // act base for compute (padded layout)
    const char* actb = (const char*)((pl == 0) ? sX : (pl == 3) ? sH1 : sH0);
    actb += kc * CHUNK_B;

    // ---- prefetch X[0] into padded sX ----
    {
        for (int j = 0; j < 8; j++) {
            int v = tid + j * 256;
            int bb = v >> 8, w32 = v & 255;
            int tk = __ldg(tokens + bb * SEQ + 0);
            float4 x = make_float4(0.f, 0.f, 0.f, 0.f);
            if (tk != 0) x = __ldg((const float4*)(emb + (size_t)tk * DIM + w32 * 4));
            *(float4*)((char*)sX + bb * ROW_B + (w32 >> 5) * CHUNK_B + (w32 & 31) * 16) = x;
        }
    }
    grid_barrier();

    for (int s = 0; s <= SEQ; s++) {
        const int pr = (s + 1) & 1;

        // ---- stage h0[s-1], h1[s-2]: batched ldcg -> padded STS ----
        {
            const float4* h0s = (const float4*)&g_h0[pr][0][0];
            const float4* h1s = (const float4*)&g_h1[pr][0][0];
            float4 r0[8], r1[8];
            #pragma unroll
            for (int j = 0; j < 8; j++) {
                r0[j] = __ldcg(h0s + tid + j * 256);
                r1[j] = __ldcg(h1s + tid + j * 256);
            }
            #pragma unroll
            for (int j = 0; j < 8; j++) {
                int v = tid + j * 256;
                int bb = v >> 8, w32 = v & 255;
                size_t off = bb * ROW_B + (w32 >> 5) * CHUNK_B + (w32 & 31) * 16;
                *(float4*)((char*)sH0 + off) = r0[j];
                *(float4*)((char*)sH1 + off) = r1[j];
            }
        }
        __syncthreads();

        // ---- compute: 8 batches x 128-K chunk, weights in regs ----
        {
            u64 acc[8];
            #pragma unroll
            for (int b = 0; b < 8; b++) acc[b] = 0ull;
            #pragma unroll
            for (int t = 0; t < 32; t++) {
                #pragma unroll
                for (int b = 0; b < 8; b++) {
                    ulonglong2 v = *(const ulonglong2*)(actb + b * ROW_B + t * 16);
                    fmaX2(acc[b], v.x, w[2 * t]);
                    fmaX2(acc[b], v.y, w[2 * t + 1]);
                }
            }
            float* sr = sred + tid * 8;
            #pragma unroll
            for (int b = 0; b < 8; b++) sr[b] = sum2(acc[b]);
        }
        __syncthreads();

        // ---- reduce 16 partials (2 pl x 8 kc) per output, tanh, store ----
        if (tid < 128) {
            const float* base = sred + (olyr * 2) * 512 + ojj * 8 + ob;
            float v = bo;
            #pragma unroll
            for (int q = 0; q < 16; q++) v += base[q * 64];
            float hv = tanhf(v);
            if (olyr == 0) {
                if (s < SEQ) g_h0[s & 1][ob][j0 + ojj] = hv;
            } else if (s >= 1) {
                g_h1[s & 1][ob][j0 + ojj] = hv;
                g_rnn_out[(size_t)(ob * SEQ + (s - 1)) * DIM + j0 + ojj] = hv;
            }
        }

        // ---- prefetch X[s+1] BEFORE the barrier ----
        if (s + 1 < SEQ) {
            for (int j = 0; j < 8; j++) {
                int v = tid + j * 256;
                int bb = v >> 8, w32 = v & 255;
                int tk = __ldg(tokens + bb * SEQ + (s + 1));
                float4 x = make_float4(0.f, 0.f, 0.f, 0.f);
                if (tk != 0) x = __ldg((const float4*)(emb + (size_t)tk * DIM + w32 * 4));
                *(float4*)((char*)sX + bb * ROW_B + (w32 >> 5) * CHUNK_B + (w32 & 31) * 16) = x;
            }
        }
        grid_barrier();
    }
}

// =====================================================================
// Convert A: g_rnn_out fp32 -> hi/lo bf16 (same layout, K-major)
// =====================================================================
__global__ void __launch_bounds__(256)
convA_kernel()
{
    int v = blockIdx.x * 256 + threadIdx.x;           // float4 index
    const float4* src = (const float4*)g_rnn_out;
    float4 x = src[v];
    __nv_bfloat16 hi[4], lo[4];
    float xs[4] = {x.x, x.y, x.z, x.w};
    #pragma unroll
    for (int i = 0; i < 4; i++) {
        hi[i] = __float2bfloat16(xs[i]);
        lo[i] = __float2bfloat16(xs[i] - __bfloat162float(hi[i]));
    }
    *(uint2*)(g_Ahi + (size_t)v * 4) = *(uint2*)hi;
    *(uint2*)(g_Alo + (size_t)v * 4) = *(uint2*)lo;
}

// =====================================================================
// Convert + transpose W: fc_w[k][n] fp32 -> g_WhiT/g_WloT[n][k] bf16
// =====================================================================
__global__ void __launch_bounds__(256)
convW_kernel(const float* __restrict__ W)
{
    __shared__ float s[32][36];
    const int n0 = blockIdx.x * 32;
    const int k0 = blockIdx.y * 32;
    const int tid = threadIdx.x;
    const int ty = tid >> 3;
    const int tx = (tid & 7) << 2;

    float4 v = *(const float4*)(W + (size_t)(k0 + ty) * NVOC + n0 + tx);
    s[ty][tx + 0] = v.x; s[ty][tx + 1] = v.y;
    s[ty][tx + 2] = v.z; s[ty][tx + 3] = v.w;
    __syncthreads();

    const int r  = tid >> 3;
    const int c4 = (tid & 7) << 2;
    __nv_bfloat16 hi[4], lo[4];
    #pragma unroll
    for (int j = 0; j < 4; j++) {
        float x = s[c4 + j][r];
        hi[j] = __float2bfloat16(x);
        lo[j] = __float2bfloat16(x - __bfloat162float(hi[j]));
    }
    size_t off = (size_t)(n0 + r) * DIM + k0 + c4;
    *(uint2*)(g_WhiT + off) = *(uint2*)hi;
    *(uint2*)(g_WloT + off) = *(uint2*)lo;
}

// =====================================================================
// HMMA projection: C[4096,32064] = A @ W^T + bias, split-bf16 (3 products).
// CTA 128x128xK32, 8 warps (2x4), warp tile 64x32 = 4x4 m16n8k16 frags.
// cp.async double-buffered smem; 80B row stride. Grid M-fastest.
// =====================================================================
#define GSTRIDE 80
#define GTILE   (128 * GSTRIDE)
#define OFF_AHI 0
#define OFF_ALO (1 * GTILE)
#define OFF_BHI (2 * GTILE)
#define OFF_BLO (3 * GTILE)
#define STAGE_BYTES (4 * GTILE)
#define GEMM_SMEM (2 * STAGE_BYTES)
#define NKT (DIM / 32)

__global__ void __launch_bounds__(256, 1)
gemm_hmma_kernel(const float* __restrict__ bias, float* __restrict__ C)
{
    extern __shared__ __align__(16) char smc[];
    const u32 sb = smem_u32(smc);
    const int tid = threadIdx.x;
    const int wid = tid >> 5;
    const int lane = tid & 31;
    const int wm = wid & 1;
    const int wn = wid >> 1;
    const int row0 = blockIdx.x * 128;
    const int col0 = blockIdx.y * 128;

    const int c0r = (tid) >> 2,        c0v = (tid) & 3;
    const int c1r = (tid + 256) >> 2,  c1v = (tid + 256) & 3;
    const u32 s0 = (u32)(c0r * GSTRIDE + c0v * 16);
    const u32 s1 = (u32)(c1r * GSTRIDE + c1v * 16);
    const size_t ga0 = (size_t)(row0 + c0r) * DIM + c0v * 8;
    const size_t ga1 = (size_t)(row0 + c1r) * DIM + c1v * 8;
    const size_t gb0 = (size_t)(col0 + c0r) * DIM + c0v * 8;
    const size_t gb1 = (size_t)(col0 + c1r) * DIM + c1v * 8;

    const u32 aRowOff = (u32)((wm * 64 + (lane & 7) + ((lane >> 3) & 1) * 8) * GSTRIDE
                              + (lane >> 4) * 16);
    const u32 bRowOff = (u32)((wn * 32 + (lane & 7) + (lane >> 4) * 8) * GSTRIDE
                              + ((lane >> 3) & 1) * 16);

    float acc[4][4][4];
    #pragma unroll
    for (int i = 0; i < 4; i++)
        #pragma unroll
        for (int j = 0; j < 4; j++)
            #pragma unroll
            for (int q = 0; q < 4; q++) acc[i][j][q] = 0.f;

    {
        u32 st = sb;
        CP_ASYNC16(st + OFF_AHI + s0, g_Ahi + ga0);
        CP_ASYNC16(st + OFF_AHI + s1, g_Ahi + ga1);
        CP_ASYNC16(st + OFF_ALO + s0, g_Alo + ga0);
        CP_ASYNC16(st + OFF_ALO + s1, g_Alo + ga1);
        CP_ASYNC16(st + OFF_BHI + s0, g_WhiT + gb0);
        CP_ASYNC16(st + OFF_BHI + s1, g_WhiT + gb1);
        CP_ASYNC16(st + OFF_BLO + s0, g_WloT + gb0);
        CP_ASYNC16(st + OFF_BLO + s1, g_WloT + gb1);
        CP_COMMIT();
    }

    for (int kt = 0; kt < NKT; kt++) {
        if (kt + 1 < NKT) {
            const int kc = (kt + 1) * 32;
            u32 st = sb + ((kt + 1) & 1) * STAGE_BYTES;
            CP_ASYNC16(st + OFF_AHI + s0, g_Ahi + ga0 + kc);
            CP_ASYNC16(st + OFF_AHI + s1, g_Ahi + ga1 + kc);
            CP_ASYNC16(st + OFF_ALO + s0, g_Alo + ga0 + kc);
            CP_ASYNC16(st + OFF_ALO + s1, g_Alo + ga1 + kc);
            CP_ASYNC16(st + OFF_BHI + s0, g_WhiT + gb0 + kc);
            CP_ASYNC16(st + OFF_BHI + s1, g_WhiT + gb1 + kc);
            CP_ASYNC16(st + OFF_BLO + s0, g_WloT + gb0 + kc);
            CP_ASYNC16(st + OFF_BLO + s1, g_WloT + gb1 + kc);
            CP_COMMIT();
            CP_WAIT(1);
        } else {
            CP_WAIT(0);
        }
        __syncthreads();

        const u32 st = sb + (kt & 1) * STAGE_BYTES;
        const u32 aHi = st + OFF_AHI + aRowOff;
        const u32 aLo = st + OFF_ALO + aRowOff;
        const u32 bHi = st + OFF_BHI + bRowOff;
        const u32 bLo = st + OFF_BLO + bRowOff;

        #pragma unroll
        for (int ks = 0; ks < 2; ks++) {
            u32 ah[4][4], al[4][4], bh[2][4], bl[2][4];
            #pragma unroll
            for (int mt = 0; mt < 4; mt++) {
                ldsm4(ah[mt], aHi + mt * (16 * GSTRIDE) + ks * 32);
                ldsm4(al[mt], aLo + mt * (16 * GSTRIDE) + ks * 32);
            }
            #pragma unroll
            for (int g = 0; g < 2; g++) {
                ldsm4(bh[g], bHi + g * (16 * GSTRIDE) + ks * 32);
                ldsm4(bl[g], bLo + g * (16 * GSTRIDE) + ks * 32);
            }
            #pragma unroll
            for (int mt = 0; mt < 4; mt++)
                #pragma unroll
                for (int nt = 0; nt < 4; nt++) {
                    float* c = acc[mt][nt];
                    const u32* bhp = &bh[nt >> 1][(nt & 1) * 2];
                    const u32* blp = &bl[nt >> 1][(nt & 1) * 2];
                    mma16816(c, ah[mt], bhp);
                    mma16816(c, ah[mt], blp);
                    mma16816(c, al[mt], bhp);
                }
        }
        __syncthreads();
    }

    #pragma unroll
    for (int nt = 0; nt < 4; nt++) {
        const int n = col0 + wn * 32 + nt * 8 + (lane & 3) * 2;
        if (n >= NVOC) continue;
        const float b0 = __ldg(bias + n);
        const float b1 = __ldg(bias + n + 1);
        #pragma unroll
        for (int mt = 0; mt < 4; mt++) {
            const int m = row0 + wm * 64 + mt * 16 + (lane >> 2);
            float* cp0 = C + (size_t)m * NVOC + n;
            float* cp1 = C + (size_t)(m + 8) * NVOC + n;
            *(float2*)cp0 = make_float2(acc[mt][nt][0] + b0, acc[mt][nt][1] + b1);
            *(float2*)cp1 = make_float2(acc[mt][nt][2] + b0, acc[mt][nt][3] + b1);
        }
    }
}

// =====================================================================
extern "C" void kernel_launch(void* const* d_in, const int* in_sizes, int n_in,
                              void* d_out, int out_size)
{
    const int*   tokens = (const int*)  d_in[0];
    const float* emb    = (const float*)d_in[1];
    const float* Wh     = (const float*)d_in[2];
    const float* Uh     = (const float*)d_in[3];
    const float* b      = (const float*)d_in[4];
    const float* fc_w   = (const float*)d_in[5];
    const float* fc_b   = (const float*)d_in[6];
    float* C = (float*)d_out;
    (void)in_sizes; (void)n_in; (void)out_size;

    cudaFuncSetAttribute(rnn_kernel,
                         cudaFuncAttributeMaxDynamicSharedMemorySize, RNN_SMEM);
    cudaFuncSetAttribute(gemm_hmma_kernel,
                         cudaFuncAttributeMaxDynamicSharedMemorySize, GEMM_SMEM);

    dim3 wgrid(NVOC / 32, DIM / 32);
    convW_kernel<<<wgrid, 256>>>(fc_w);

    rnn_kernel<<<NCTA, RNN_THREADS, RNN_SMEM>>>(tokens, emb, Wh, Uh, b);

    convA_kernel<<<(BATCH * SEQ * DIM / 4) / 256, 256>>>();

    dim3 ggrid((BATCH * SEQ) / 128, NVOC_PAD / 128);
    gemm_hmma_kernel<<<ggrid, 256, GEMM_SMEM>>>(fc_b, C);
}